// round 2
// baseline (speedup 1.0000x reference)
#include <cuda_runtime.h>
#include <cuda_bf16.h>
#include <math.h>
#include <float.h>

// Problem constants
#define BB 2
#define SS 2048
#define HH 4096
#define NHEAD 32
#define NKVH 2
#define HDIM 128
#define ROT 64
#define QKV_N ((NHEAD + 2*NKVH) * HDIM)   // 4608
#define TOKENS (BB*SS)                     // 4096

// Scratch (device globals; allocation-free)
__device__ float g_qkv[(size_t)TOKENS * QKV_N];    // 75.5 MB
__device__ float g_attn[(size_t)TOKENS * HH];      // 67 MB

// ---------------------------------------------------------------------------
// Tiled SGEMM: C[M,N] = A[M,K] @ B[K,N] (+ bias). BM=BN=128, BK=16, 256 thr,
// 8x8 per-thread micro-tile. All dims are multiples of tile sizes here.
// ---------------------------------------------------------------------------
template<bool HAS_BIAS>
__global__ __launch_bounds__(256)
void sgemm_kernel(const float* __restrict__ A, const float* __restrict__ B,
                  const float* __restrict__ bias, float* __restrict__ C,
                  int M, int N, int K)
{
    __shared__ float As[16][132];   // transposed: As[k][m]
    __shared__ float Bs[16][132];   // Bs[k][n]

    const int tid = threadIdx.x;
    const int tr = tid >> 4;        // 0..15
    const int tc = tid & 15;        // 0..15
    const int rowBase = blockIdx.y * 128;
    const int colBase = blockIdx.x * 128;

    float acc[8][8];
    #pragma unroll
    for (int i = 0; i < 8; ++i)
        #pragma unroll
        for (int j = 0; j < 8; ++j) acc[i][j] = 0.f;

    for (int kt = 0; kt < K; kt += 16) {
        // Load A tile (128 rows x 16 k), store transposed
        #pragma unroll
        for (int r = 0; r < 2; ++r) {
            int f = tid + r * 256;            // 0..511 float4 slots
            int ar = f >> 2;                  // row in tile
            int ak = (f & 3) * 4;             // k offset
            float4 v = *(const float4*)&A[(size_t)(rowBase + ar) * K + kt + ak];
            As[ak + 0][ar] = v.x;
            As[ak + 1][ar] = v.y;
            As[ak + 2][ar] = v.z;
            As[ak + 3][ar] = v.w;
        }
        // Load B tile (16 k rows x 128 cols)
        #pragma unroll
        for (int r = 0; r < 2; ++r) {
            int f = tid + r * 256;
            int bk = f >> 5;                  // 0..15
            int bc = (f & 31) * 4;            // 0..124
            *(float4*)&Bs[bk][bc] = *(const float4*)&B[(size_t)(kt + bk) * N + colBase + bc];
        }
        __syncthreads();

        #pragma unroll
        for (int k = 0; k < 16; ++k) {
            float a[8], b[8];
            float4 a0 = *(float4*)&As[k][tr * 8];
            float4 a1 = *(float4*)&As[k][tr * 8 + 4];
            float4 b0 = *(float4*)&Bs[k][tc * 8];
            float4 b1 = *(float4*)&Bs[k][tc * 8 + 4];
            a[0]=a0.x; a[1]=a0.y; a[2]=a0.z; a[3]=a0.w;
            a[4]=a1.x; a[5]=a1.y; a[6]=a1.z; a[7]=a1.w;
            b[0]=b0.x; b[1]=b0.y; b[2]=b0.z; b[3]=b0.w;
            b[4]=b1.x; b[5]=b1.y; b[6]=b1.z; b[7]=b1.w;
            #pragma unroll
            for (int i = 0; i < 8; ++i)
                #pragma unroll
                for (int j = 0; j < 8; ++j)
                    acc[i][j] = fmaf(a[i], b[j], acc[i][j]);
        }
        __syncthreads();
    }

    // Epilogue
    #pragma unroll
    for (int i = 0; i < 8; ++i) {
        int row = rowBase + tr * 8 + i;
        float* cptr = &C[(size_t)row * N + colBase + tc * 8];
        #pragma unroll
        for (int j = 0; j < 8; ++j) {
            float v = acc[i][j];
            if (HAS_BIAS) v += bias[colBase + tc * 8 + j];
            cptr[j] = v;
        }
    }
}

// ---------------------------------------------------------------------------
// GLM RoPE, in-place on g_qkv. Rotates interleaved pairs of first ROT dims of
// each of the 32 Q heads and 2 K heads. V untouched.
// ---------------------------------------------------------------------------
__global__ void rope_kernel(float* __restrict__ qkv, const int* __restrict__ positions)
{
    int idx = blockIdx.x * blockDim.x + threadIdx.x;
    const int total = TOKENS * (NHEAD + NKVH) * (ROT / 2);   // 4096*34*32
    if (idx >= total) return;
    int i    = idx & 31;                  // pair index 0..31
    int head = (idx >> 5) % (NHEAD + NKVH);
    int tok  = idx / ((NHEAD + NKVH) * 32);

    float pos = (float)positions[tok];
    // inv_freq = 10000^(-i/32), fp32 like the reference
    float inv = __powf(10000.0f, -(float)i * (1.0f / 32.0f));
    float ang = pos * inv;
    float c, s;
    sincosf(ang, &s, &c);
    // note: sincosf(x, &sin, &cos)
    int col = (head < NHEAD) ? head * HDIM : (NHEAD * HDIM + (head - NHEAD) * HDIM);
    float* p = qkv + (size_t)tok * QKV_N + col + 2 * i;
    float x1 = p[0], x2 = p[1];
    p[0] = x1 * c - x2 * s;
    p[1] = x1 * s + x2 * c;
}

// ---------------------------------------------------------------------------
// Flash attention, fp32. BQ=BK=64, 256 threads.
// Thread (ty,tx) with ty=tid/16, tx=tid%16:
//   - scores: 4 q-rows (4*ty..) x 4 k-cols (4*tx..)
//   - output: same 4 q-rows x 8 d-cols (8*tx..)
// Row softmax stats reduced over tx lanes via shfl_xor (1,2,4,8).
// ---------------------------------------------------------------------------
__global__ __launch_bounds__(256)
void flash_kernel(const float* __restrict__ qkv, float* __restrict__ attn_out)
{
    const int qt = blockIdx.x;              // 0..31 query tile
    const int bh = blockIdx.y;              // 0..63
    const int b  = bh >> 5;
    const int h  = bh & 31;
    const int kvh = h >> 4;                 // GQA group

    extern __shared__ float sm[];
    float* Qs = sm;                         // 64 x 132
    float* Ks = Qs + 64 * 132;              // 64 x 132
    float* Vs = Ks + 64 * 132;              // 64 x 132
    float* Ps = Vs + 64 * 132;              // 64 x 68

    const int tid = threadIdx.x;
    const int ty = tid >> 4;                // 0..15
    const int tx = tid & 15;                // 0..15
    const float scale = 0.08838834764831845f;  // 128^-0.5

    // Load Q tile: 64 rows x 128 dims
    const float* qbase = qkv + (size_t)(b * SS + qt * 64) * QKV_N + h * HDIM;
    #pragma unroll
    for (int r = 0; r < 8; ++r) {
        int lin = r * 1024 + tid * 4;
        int row = lin >> 7, col = lin & 127;
        *(float4*)&Qs[row * 132 + col] = *(const float4*)(qbase + (size_t)row * QKV_N + col);
    }

    float m_i[4], l_i[4], acc[4][8];
    #pragma unroll
    for (int i = 0; i < 4; ++i) {
        m_i[i] = -3.0e38f; l_i[i] = 0.f;
        #pragma unroll
        for (int j = 0; j < 8; ++j) acc[i][j] = 0.f;
    }
    __syncthreads();

    for (int kt = 0; kt <= qt; ++kt) {
        const float* kbase = qkv + (size_t)(b * SS + kt * 64) * QKV_N + NHEAD * HDIM + kvh * HDIM;
        const float* vbase = kbase + NKVH * HDIM;
        #pragma unroll
        for (int r = 0; r < 8; ++r) {
            int lin = r * 1024 + tid * 4;
            int row = lin >> 7, col = lin & 127;
            *(float4*)&Ks[row * 132 + col] = *(const float4*)(kbase + (size_t)row * QKV_N + col);
            *(float4*)&Vs[row * 132 + col] = *(const float4*)(vbase + (size_t)row * QKV_N + col);
        }
        __syncthreads();

        // S = Q K^T (4x4 per thread)
        float s[4][4];
        #pragma unroll
        for (int i = 0; i < 4; ++i)
            #pragma unroll
            for (int j = 0; j < 4; ++j) s[i][j] = 0.f;

        for (int d = 0; d < 128; d += 4) {
            float4 qv[4], kv[4];
            #pragma unroll
            for (int i = 0; i < 4; ++i) qv[i] = *(float4*)&Qs[(ty * 4 + i) * 132 + d];
            #pragma unroll
            for (int j = 0; j < 4; ++j) kv[j] = *(float4*)&Ks[(tx * 4 + j) * 132 + d];
            #pragma unroll
            for (int i = 0; i < 4; ++i)
                #pragma unroll
                for (int j = 0; j < 4; ++j) {
                    s[i][j] = fmaf(qv[i].x, kv[j].x, s[i][j]);
                    s[i][j] = fmaf(qv[i].y, kv[j].y, s[i][j]);
                    s[i][j] = fmaf(qv[i].z, kv[j].z, s[i][j]);
                    s[i][j] = fmaf(qv[i].w, kv[j].w, s[i][j]);
                }
        }
        // scale + causal mask (only diagonal tile)
        #pragma unroll
        for (int i = 0; i < 4; ++i)
            #pragma unroll
            for (int j = 0; j < 4; ++j) {
                s[i][j] *= scale;
                if (kt == qt && (tx * 4 + j) > (ty * 4 + i)) s[i][j] = -3.0e38f;
            }

        // Online softmax per row (reduce over the 16 tx lanes)
        float alpha[4];
        #pragma unroll
        for (int i = 0; i < 4; ++i) {
            float mx = s[i][0];
            mx = fmaxf(mx, s[i][1]); mx = fmaxf(mx, s[i][2]); mx = fmaxf(mx, s[i][3]);
            #pragma unroll
            for (int o = 1; o < 16; o <<= 1)
                mx = fmaxf(mx, __shfl_xor_sync(0xffffffffu, mx, o));
            float newm = fmaxf(m_i[i], mx);
            alpha[i] = __expf(m_i[i] - newm);
            m_i[i] = newm;
            float rs = 0.f;
            #pragma unroll
            for (int j = 0; j < 4; ++j) {
                float p = __expf(s[i][j] - newm);
                s[i][j] = p;
                rs += p;
            }
            #pragma unroll
            for (int o = 1; o < 16; o <<= 1)
                rs += __shfl_xor_sync(0xffffffffu, rs, o);
            l_i[i] = l_i[i] * alpha[i] + rs;
        }

        // Stash P, rescale accumulators
        #pragma unroll
        for (int i = 0; i < 4; ++i) {
            #pragma unroll
            for (int j = 0; j < 4; ++j)
                Ps[(ty * 4 + i) * 68 + tx * 4 + j] = s[i][j];
            #pragma unroll
            for (int j = 0; j < 8; ++j) acc[i][j] *= alpha[i];
        }
        __syncthreads();

        // O += P @ V
        for (int k = 0; k < 64; ++k) {
            float pk[4];
            #pragma unroll
            for (int i = 0; i < 4; ++i) pk[i] = Ps[(ty * 4 + i) * 68 + k];
            float4 v0 = *(float4*)&Vs[k * 132 + tx * 8];
            float4 v1 = *(float4*)&Vs[k * 132 + tx * 8 + 4];
            #pragma unroll
            for (int i = 0; i < 4; ++i) {
                acc[i][0] = fmaf(pk[i], v0.x, acc[i][0]);
                acc[i][1] = fmaf(pk[i], v0.y, acc[i][1]);
                acc[i][2] = fmaf(pk[i], v0.z, acc[i][2]);
                acc[i][3] = fmaf(pk[i], v0.w, acc[i][3]);
                acc[i][4] = fmaf(pk[i], v1.x, acc[i][4]);
                acc[i][5] = fmaf(pk[i], v1.y, acc[i][5]);
                acc[i][6] = fmaf(pk[i], v1.z, acc[i][6]);
                acc[i][7] = fmaf(pk[i], v1.w, acc[i][7]);
            }
        }
        __syncthreads();
    }

    // Epilogue: normalize and write out [token][h*128 + d]
    float* obase = attn_out + (size_t)(b * SS + qt * 64) * HH + h * HDIM;
    #pragma unroll
    for (int i = 0; i < 4; ++i) {
        float inv_l = 1.0f / l_i[i];
        int row = ty * 4 + i;
        float4 o0, o1;
        o0.x = acc[i][0] * inv_l; o0.y = acc[i][1] * inv_l;
        o0.z = acc[i][2] * inv_l; o0.w = acc[i][3] * inv_l;
        o1.x = acc[i][4] * inv_l; o1.y = acc[i][5] * inv_l;
        o1.z = acc[i][6] * inv_l; o1.w = acc[i][7] * inv_l;
        *(float4*)(obase + (size_t)row * HH + tx * 8)     = o0;
        *(float4*)(obase + (size_t)row * HH + tx * 8 + 4) = o1;
    }
}

// ---------------------------------------------------------------------------
extern "C" void kernel_launch(void* const* d_in, const int* in_sizes, int n_in,
                              void* d_out, int out_size)
{
    const float* hs      = (const float*)d_in[0];
    const float* w_qkv   = (const float*)d_in[1];
    const float* b_qkv   = (const float*)d_in[2];
    const float* w_dense = (const float*)d_in[3];
    const int*   pos     = (const int*)d_in[4];
    float* out = (float*)d_out;

    float *qkv_ptr, *attn_ptr;
    cudaGetSymbolAddress((void**)&qkv_ptr, g_qkv);
    cudaGetSymbolAddress((void**)&attn_ptr, g_attn);

    // 1) QKV projection + bias: [4096,4096] @ [4096,4608]
    sgemm_kernel<true><<<dim3(QKV_N / 128, TOKENS / 128), 256>>>(
        hs, w_qkv, b_qkv, qkv_ptr, TOKENS, QKV_N, HH);

    // 2) RoPE in place
    {
        int total = TOKENS * (NHEAD + NKVH) * (ROT / 2);
        rope_kernel<<<(total + 255) / 256, 256>>>(qkv_ptr, pos);
    }

    // 3) Flash attention
    {
        size_t smem = (3 * 64 * 132 + 64 * 68) * sizeof(float);  // ~116 KB
        cudaFuncSetAttribute(flash_kernel, cudaFuncAttributeMaxDynamicSharedMemorySize, (int)smem);
        flash_kernel<<<dim3(SS / 64, BB * NHEAD), 256, smem>>>(qkv_ptr, attn_ptr);
    }

    // 4) Dense projection: [4096,4096] @ [4096,4096]
    sgemm_kernel<false><<<dim3(HH / 128, TOKENS / 128), 256>>>(
        attn_ptr, w_dense, nullptr, out, TOKENS, HH, HH);
}